// round 2
// baseline (speedup 1.0000x reference)
#include <cuda_runtime.h>

// out[b,j,h] = (1/N) * sum_i sum_g W[b,i,j,h,g] * x[b,i,g]
// B=16, N=32, H=64. W: 256 MiB fp32 streamed once -> pure HBM-bound.
//
// R2 changes vs R1 (43.1us, DRAM 82%):
//  - split each (b,j) into 2 i-halves -> 1024 CTAs x 256KB (finer balance)
//  - explicit 3-buffer register pipeline: 12 LDG.128 in flight per warp
//  - __ldcs streaming loads on W
//  - atomicAdd combine (exactly 2 commutative addends -> deterministic),
//    zero-init kernel first.

#define BB 16
#define NN 32
#define HH 64
#define ISPLIT 2
#define IPER (NN / ISPLIT)          // 16 i's per CTA

__global__ void zero_out_kernel(float* __restrict__ out) {
    out[blockIdx.x * 256 + threadIdx.x] = 0.0f;
}

__global__ __launch_bounds__(256, 3)
void msg_nn_kernel(const float4* __restrict__ W,
                   const float4* __restrict__ X,
                   float* __restrict__ out)
{
    const int blk  = blockIdx.x;        // 0..1023
    const int bj   = blk >> 1;          // 0..511
    const int half = blk & 1;
    const int b    = bj >> 5;
    const int j    = bj & (NN - 1);
    const int i0   = half * IPER;

    // x[b, i0:i0+16, :] -> 16 i's * 16 float4 = 256 float4 = 4 KB
    __shared__ float4 xs[IPER * 16];

    const int t = threadIdx.x;          // 0..255
    const float4* xb = X + (size_t)b * (NN * HH / 4) + (size_t)i0 * 16;
    xs[t] = xb[t];
    __syncthreads();

    const int g4 = t & 15;
    const int h0 = t >> 4;

    const size_t tileF4 = (size_t)HH * HH / 4;       // 1024
    const size_t IS     = (size_t)NN * tileF4;       // 32768 (i stride in float4)
    const float4* Wp = W + ((size_t)b * NN + i0) * IS + (size_t)j * tileF4 + t;

    // 3-buffer software pipeline: A = current, B = +1, C = +2 (being loaded)
    float4 A0 = __ldcs(Wp);       float4 A1 = __ldcs(Wp + 256);
    float4 A2 = __ldcs(Wp + 512); float4 A3 = __ldcs(Wp + 768);
    float4 B0 = __ldcs(Wp + IS);       float4 B1 = __ldcs(Wp + IS + 256);
    float4 B2 = __ldcs(Wp + IS + 512); float4 B3 = __ldcs(Wp + IS + 768);

    float acc0 = 0.f, acc1 = 0.f, acc2 = 0.f, acc3 = 0.f;

    #pragma unroll
    for (int i = 0; i < IPER; ++i) {
        float4 C0, C1, C2, C3;
        if (i < IPER - 2) {
            const float4* Wn = Wp + 2 * IS;
            C0 = __ldcs(Wn);       C1 = __ldcs(Wn + 256);
            C2 = __ldcs(Wn + 512); C3 = __ldcs(Wn + 768);
        } else {
            C0 = C1 = C2 = C3 = make_float4(0.f, 0.f, 0.f, 0.f);
        }

        const float4 xv = xs[i * 16 + g4];
        acc0 += A0.x * xv.x + A0.y * xv.y + A0.z * xv.z + A0.w * xv.w;
        acc1 += A1.x * xv.x + A1.y * xv.y + A1.z * xv.z + A1.w * xv.w;
        acc2 += A2.x * xv.x + A2.y * xv.y + A2.z * xv.z + A2.w * xv.w;
        acc3 += A3.x * xv.x + A3.y * xv.y + A3.z * xv.z + A3.w * xv.w;

        A0 = B0; A1 = B1; A2 = B2; A3 = B3;
        B0 = C0; B1 = C1; B2 = C2; B3 = C3;
        Wp += IS;
    }

    // Reduce 16 g-quads per h within each contiguous 16-lane group.
    const unsigned mask = 0xFFFFFFFFu;
    #pragma unroll
    for (int off = 8; off > 0; off >>= 1) {
        acc0 += __shfl_down_sync(mask, acc0, off);
        acc1 += __shfl_down_sync(mask, acc1, off);
        acc2 += __shfl_down_sync(mask, acc2, off);
        acc3 += __shfl_down_sync(mask, acc3, off);
    }

    if (g4 == 0) {
        const float s = 1.0f / (float)NN;
        float* o = out + (size_t)bj * HH + h0;
        atomicAdd(o +  0, acc0 * s);
        atomicAdd(o + 16, acc1 * s);
        atomicAdd(o + 32, acc2 * s);
        atomicAdd(o + 48, acc3 * s);
    }
}

extern "C" void kernel_launch(void* const* d_in, const int* in_sizes, int n_in,
                              void* d_out, int out_size)
{
    const float4* W = (const float4*)d_in[0];   // edge_wgt [B,N,N,H,H] fp32
    const float4* X = (const float4*)d_in[1];   // node_hidden [B,N,H] fp32
    float* out = (float*)d_out;                 // [B,N,H] fp32 (poisoned)

    zero_out_kernel<<<(BB * NN * HH) / 256, 256>>>(out);   // 128 blocks
    msg_nn_kernel<<<BB * NN * ISPLIT, 256>>>(W, (const float4*)d_in[1], out);
}